// round 1
// baseline (speedup 1.0000x reference)
#include <cuda_runtime.h>
#include <cstdint>

#define N_NODES 50000
#define N_EDGES 800000
#define F_IN 256
#define HID 64
#define NCLS 16

// ---------------- scratch (static __device__, no runtime allocation) ----------------
__device__ int   g_cnt[N_NODES];
__device__ int   g_rowptr[N_NODES + 1];
__device__ int   g_cursor[N_NODES];
__device__ int   g_es[N_EDGES];
__device__ float g_ep[N_EDGES];
__device__ float g_rdeg[N_NODES];
__device__ float g_Y[(size_t)N_NODES * 192];     // [N, 3*Cout]: y0 | (y1-y0) | x@R+b
__device__ float g_h[(size_t)N_NODES * HID];
__device__ float g_mid[(size_t)N_NODES * HID];
__device__ float g_kv[(size_t)N_NODES * HID];
__device__ float g_acc[(size_t)N_NODES * HID];
__device__ float g_cur[(size_t)N_NODES * HID];
__device__ float g_logits[(size_t)N_NODES * NCLS];

// ---------------- packed f32x2 helpers (sm_103a FFMA2) ----------------
__device__ __forceinline__ void fma2(unsigned long long& acc, unsigned long long a, unsigned long long b) {
    asm("fma.rn.f32x2 %0, %1, %2, %0;" : "+l"(acc) : "l"(a), "l"(b));
}
__device__ __forceinline__ unsigned long long dup2(float a) {
    unsigned long long r; asm("mov.b64 %0, {%1, %1};" : "=l"(r) : "f"(a)); return r;
}
__device__ __forceinline__ float2 unpk(unsigned long long v) {
    float2 r; asm("mov.b64 {%0, %1}, %2;" : "=f"(r.x), "=f"(r.y) : "l"(v)); return r;
}

// ---------------- CSR build ----------------
__global__ void k_zero_cnt() {
    int i = blockIdx.x * blockDim.x + threadIdx.x;
    if (i < N_NODES) g_cnt[i] = 0;
}
__global__ void k_count(const int* __restrict__ dst) {
    int e = blockIdx.x * blockDim.x + threadIdx.x;
    if (e < N_EDGES) atomicAdd(&g_cnt[dst[e]], 1);
}
__global__ void k_scan() {
    __shared__ int ss[1024];
    int tid = threadIdx.x;
    const int CH = (N_NODES + 1023) / 1024;
    int base = tid * CH;
    int s = 0;
    for (int i = 0; i < CH; ++i) { int idx = base + i; if (idx < N_NODES) s += g_cnt[idx]; }
    ss[tid] = s;
    __syncthreads();
    for (int off = 1; off < 1024; off <<= 1) {
        int v = (tid >= off) ? ss[tid - off] : 0;
        __syncthreads();
        ss[tid] += v;
        __syncthreads();
    }
    int run = ss[tid] - s;   // exclusive prefix of this thread's chunk
    for (int i = 0; i < CH; ++i) {
        int idx = base + i;
        if (idx < N_NODES) {
            g_rowptr[idx] = run;
            g_cursor[idx] = run;
            int d = g_cnt[idx];
            g_rdeg[idx] = 1.0f / (float)(d > 0 ? d : 1);
            run += d;
        }
    }
    if (tid == 1023) g_rowptr[N_NODES] = ss[1023];
}
__global__ void k_fill(const int* __restrict__ src, const int* __restrict__ dst,
                       const float* __restrict__ ea) {
    int e = blockIdx.x * blockDim.x + threadIdx.x;
    if (e < N_EDGES) {
        int pos = atomicAdd(&g_cursor[dst[e]], 1);
        g_es[pos] = src[e];
        g_ep[pos] = ea[e];
    }
}

// ---------------- fused 3-matrix GEMM: Y = [A@W0 | A@W1 - A@W0 | A@R + b] ----------------
template <int CIN, int COUT>
__global__ void __launch_bounds__(256) k_gemm(const float* __restrict__ A,
                                              const float* __restrict__ W0,
                                              const float* __restrict__ Wk1,
                                              const float* __restrict__ R,
                                              const float* __restrict__ bias) {
    constexpr int TM = 64, TK = 16;
    constexpr int TX = COUT / 4;   // threads across columns (4 cols each)
    constexpr int TY = 256 / TX;
    constexpr int RPT = TM / TY;   // rows per thread
    __shared__ __align__(16) float As[TK][TM];
    __shared__ __align__(16) float Bs[3][TK][COUT];

    const int tid = threadIdx.x;
    const int tx = tid % TX;
    const int ty = tid / TX;
    const int m0 = blockIdx.x * TM;
    const int cb = tx * 4;

    unsigned long long acc[3][RPT][2];
#pragma unroll
    for (int m = 0; m < 3; m++)
#pragma unroll
        for (int r = 0; r < RPT; r++) { acc[m][r][0] = 0ULL; acc[m][r][1] = 0ULL; }

    for (int k0 = 0; k0 < CIN; k0 += TK) {
        {   // A tile: 16x64, transposed store
            int row = tid >> 2;
            int kq  = (tid & 3) * 4;
            float4 v = make_float4(0.f, 0.f, 0.f, 0.f);
            int gm = m0 + row;
            if (gm < N_NODES) v = *reinterpret_cast<const float4*>(A + (size_t)gm * CIN + k0 + kq);
            As[kq + 0][row] = v.x; As[kq + 1][row] = v.y;
            As[kq + 2][row] = v.z; As[kq + 3][row] = v.w;
        }
        if constexpr (COUT == 64) {
            int kk = tid >> 4, c = (tid & 15) * 4;
            *reinterpret_cast<float4*>(&Bs[0][kk][c]) = *reinterpret_cast<const float4*>(W0  + (size_t)(k0 + kk) * COUT + c);
            *reinterpret_cast<float4*>(&Bs[1][kk][c]) = *reinterpret_cast<const float4*>(Wk1 + (size_t)(k0 + kk) * COUT + c);
            *reinterpret_cast<float4*>(&Bs[2][kk][c]) = *reinterpret_cast<const float4*>(R   + (size_t)(k0 + kk) * COUT + c);
        } else {
            if (tid < TK * COUT / 4) {
                int kk = tid / (COUT / 4), c = (tid % (COUT / 4)) * 4;
                *reinterpret_cast<float4*>(&Bs[0][kk][c]) = *reinterpret_cast<const float4*>(W0  + (size_t)(k0 + kk) * COUT + c);
                *reinterpret_cast<float4*>(&Bs[1][kk][c]) = *reinterpret_cast<const float4*>(Wk1 + (size_t)(k0 + kk) * COUT + c);
                *reinterpret_cast<float4*>(&Bs[2][kk][c]) = *reinterpret_cast<const float4*>(R   + (size_t)(k0 + kk) * COUT + c);
            }
        }
        __syncthreads();
#pragma unroll
        for (int kk = 0; kk < TK; ++kk) {
            unsigned long long ap[RPT];
#pragma unroll
            for (int r = 0; r < RPT; r++) ap[r] = dup2(As[kk][ty * RPT + r]);
            const unsigned long long* b0 = reinterpret_cast<const unsigned long long*>(&Bs[0][kk][cb]);
            const unsigned long long* b1 = reinterpret_cast<const unsigned long long*>(&Bs[1][kk][cb]);
            const unsigned long long* b2 = reinterpret_cast<const unsigned long long*>(&Bs[2][kk][cb]);
            unsigned long long v00 = b0[0], v01 = b0[1];
            unsigned long long v10 = b1[0], v11 = b1[1];
            unsigned long long v20 = b2[0], v21 = b2[1];
#pragma unroll
            for (int r = 0; r < RPT; r++) {
                fma2(acc[0][r][0], ap[r], v00); fma2(acc[0][r][1], ap[r], v01);
                fma2(acc[1][r][0], ap[r], v10); fma2(acc[1][r][1], ap[r], v11);
                fma2(acc[2][r][0], ap[r], v20); fma2(acc[2][r][1], ap[r], v21);
            }
        }
        __syncthreads();
    }
    float4 bv = *reinterpret_cast<const float4*>(bias + cb);
#pragma unroll
    for (int r = 0; r < RPT; r++) {
        int gm = m0 + ty * RPT + r;
        if (gm >= N_NODES) continue;
        float* yr = g_Y + (size_t)gm * (3 * COUT);
        float2 y0a = unpk(acc[0][r][0]), y0b = unpk(acc[0][r][1]);
        float2 y1a = unpk(acc[1][r][0]), y1b = unpk(acc[1][r][1]);
        float2 xra = unpk(acc[2][r][0]), xrb = unpk(acc[2][r][1]);
        yr[cb + 0] = y0a.x;             yr[cb + 1] = y0a.y;
        yr[cb + 2] = y0b.x;             yr[cb + 3] = y0b.y;
        yr[COUT + cb + 0] = y1a.x - y0a.x; yr[COUT + cb + 1] = y1a.y - y0a.y;
        yr[COUT + cb + 2] = y1b.x - y0b.x; yr[COUT + cb + 3] = y1b.y - y0b.y;
        yr[2 * COUT + cb + 0] = xra.x + bv.x; yr[2 * COUT + cb + 1] = xra.y + bv.y;
        yr[2 * COUT + cb + 2] = xrb.x + bv.z; yr[2 * COUT + cb + 3] = xrb.y + bv.w;
    }
}

// ---------------- CSR gather aggregation + mean + residual (+tanh) ----------------
template <int COUT, bool ACT>
__global__ void __launch_bounds__(256) k_agg(float* __restrict__ out) {
    int g = blockIdx.x * blockDim.x + threadIdx.x;
    int node = g / COUT;
    int c = g % COUT;
    if (node >= N_NODES) return;
    int beg = g_rowptr[node], end = g_rowptr[node + 1];
    float acc = 0.f;
    for (int i = beg; i < end; ++i) {
        int s = g_es[i];
        float pv = g_ep[i];
        const float* yr = g_Y + (size_t)s * (3 * COUT);
        acc = fmaf(pv, yr[COUT + c], acc + yr[c]);   // y0 + p*(y1-y0)
    }
    float v = fmaf(acc, g_rdeg[node], g_Y[(size_t)node * (3 * COUT) + 2 * COUT + c]);
    if (ACT) v = tanhf(v);
    out[(size_t)node * COUT + c] = v;
}

// ---------------- RK4 elementwise ----------------
__global__ void k_rkstage(float kAccMul, float curMul, int first) {
    int i = blockIdx.x * blockDim.x + threadIdx.x;
    if (i >= N_NODES * HID) return;
    float kv = g_kv[i];
    g_acc[i] = first ? (kAccMul * kv) : fmaf(kAccMul, kv, g_acc[i]);
    g_cur[i] = fmaf(curMul, kv, g_h[i]);
}
__global__ void k_rkfinal() {
    int i = blockIdx.x * blockDim.x + threadIdx.x;
    if (i >= N_NODES * HID) return;
    g_h[i] = fmaf(0.5f, g_acc[i] + g_kv[i], g_h[i]);
}

// ---------------- log_softmax over 16 classes (half-warp per row) ----------------
__global__ void k_lsm(float* __restrict__ out) {
    int warp = (blockIdx.x * blockDim.x + threadIdx.x) >> 5;
    int lane = threadIdx.x & 31;
    int row = warp * 2 + (lane >> 4);
    int c = lane & 15;
    if (row >= N_NODES) return;
    float v = g_logits[row * 16 + c];
    float m = v;
    for (int o = 8; o > 0; o >>= 1) m = fmaxf(m, __shfl_xor_sync(0xffffffffu, m, o, 16));
    float e = expf(v - m);
    float s = e;
    for (int o = 8; o > 0; o >>= 1) s += __shfl_xor_sync(0xffffffffu, s, o, 16);
    out[row * 16 + c] = v - m - logf(s);
}

// ---------------- launch ----------------
extern "C" void kernel_launch(void* const* d_in, const int* in_sizes, int n_in,
                              void* d_out, int out_size) {
    const float* x  = (const float*)d_in[0];
    const float* ea = (const float*)d_in[1];
    const int*   src = (const int*)d_in[2];
    const int*   dst = (const int*)d_in[3];
    const float* W1 = (const float*)d_in[4];
    const float* R1 = (const float*)d_in[5];
    const float* b1 = (const float*)d_in[6];
    const float* Wa = (const float*)d_in[7];
    const float* Ra = (const float*)d_in[8];
    const float* ba = (const float*)d_in[9];
    const float* Wb = (const float*)d_in[10];
    const float* Rb = (const float*)d_in[11];
    const float* bb = (const float*)d_in[12];
    const float* W2 = (const float*)d_in[13];
    const float* R2 = (const float*)d_in[14];
    const float* b2 = (const float*)d_in[15];
    float* out = (float*)d_out;

    float *h, *mid, *kv, *cur, *logits;
    cudaGetSymbolAddress((void**)&h, g_h);
    cudaGetSymbolAddress((void**)&mid, g_mid);
    cudaGetSymbolAddress((void**)&kv, g_kv);
    cudaGetSymbolAddress((void**)&cur, g_cur);
    cudaGetSymbolAddress((void**)&logits, g_logits);

    // CSR build (per-call; graph-replayed)
    k_zero_cnt<<<(N_NODES + 255) / 256, 256>>>();
    k_count<<<N_EDGES / 256, 256>>>(dst);
    k_scan<<<1, 1024>>>();
    k_fill<<<N_EDGES / 256, 256>>>(src, dst, ea);

    const int GG = (N_NODES + 63) / 64;       // gemm grid
    const int VG = (N_NODES * HID) / 256;     // vector grid
    const int AG64 = (N_NODES * HID) / 256;   // agg grid Cout=64
    const int AG16 = (N_NODES * NCLS) / 256;  // agg grid Cout=16

    // conv1: x -> h = tanh(spline_conv(x))
    k_gemm<F_IN, HID><<<GG, 256>>>(x, W1, W1 + F_IN * HID, R1, b1);
    k_agg<HID, true><<<AG64, 256>>>(h);

    // f(y) = spline_conv(spline_conv(y; Wa,Ra,ba); Wb,Rb,bb)
    auto fstep = [&](const float* in, float* o) {
        k_gemm<HID, HID><<<GG, 256>>>(in, Wa, Wa + HID * HID, Ra, ba);
        k_agg<HID, false><<<AG64, 256>>>(mid);
        k_gemm<HID, HID><<<GG, 256>>>(mid, Wb, Wb + HID * HID, Rb, bb);
        k_agg<HID, false><<<AG64, 256>>>(o);
    };

    // RK4, one step over [0, 3]
    fstep(h, kv);                              // k1
    k_rkstage<<<VG, 256>>>(1.f, 1.5f, 1);      // acc = k1; cur = h + 1.5*k1
    fstep(cur, kv);                            // k2
    k_rkstage<<<VG, 256>>>(2.f, 1.5f, 0);      // acc += 2*k2; cur = h + 1.5*k2
    fstep(cur, kv);                            // k3
    k_rkstage<<<VG, 256>>>(2.f, 3.0f, 0);      // acc += 2*k3; cur = h + 3*k3
    fstep(cur, kv);                            // k4
    k_rkfinal<<<VG, 256>>>();                  // h += 0.5*(acc + k4)

    // conv2 + log_softmax
    k_gemm<HID, NCLS><<<GG, 256>>>(h, W2, W2 + HID * NCLS, R2, b2);
    k_agg<NCLS, true><<<AG16, 256>>>(logits);
    k_lsm<<<(N_NODES + 15) / 16, 256>>>(out);
}

// round 2
// speedup vs baseline: 1.4146x; 1.4146x over previous
#include <cuda_runtime.h>
#include <cstdint>

#define N_NODES 50000
#define N_EDGES 800000
#define F_IN 256
#define HID 64
#define NCLS 16

// ---------------- scratch (static __device__, no runtime allocation) ----------------
__device__ int   g_cnt[N_NODES];
__device__ int   g_rowptr[N_NODES + 1];
__device__ int   g_cursor[N_NODES];
__device__ int   g_es[N_EDGES];
__device__ float g_ep[N_EDGES];
__device__ float g_rdeg[N_NODES];
__device__ __align__(16) float g_Y[(size_t)N_NODES * 192];   // A-staging / conv outputs
__device__ __align__(16) float g_h[(size_t)N_NODES * HID];
__device__ __align__(16) float g_mid[(size_t)N_NODES * HID];
__device__ __align__(16) float g_kv[(size_t)N_NODES * HID];
__device__ __align__(16) float g_acc[(size_t)N_NODES * HID];
__device__ __align__(16) float g_cur[(size_t)N_NODES * HID];
__device__ __align__(16) float g_logits[(size_t)N_NODES * NCLS];
// concatenated weights (built per launch)
__device__ __align__(16) float g_B1[256 * 192];    // [K=256][N=192] = [W1_0 | W1_1 | R1]
__device__ __align__(16) float g_Bh1[192 * 64];    // rows [Ra; Wa0; Wa1]
__device__ __align__(16) float g_Bh2[192 * 64];    // rows [Rb; Wb0; Wb1]
__device__ __align__(16) float g_B2[64 * 48];      // [W2_0 | W2_1 | R2]
__device__ float g_bias1[192];
__device__ float g_bias2[48];

// ---------------- tf32 mma helpers ----------------
__device__ __forceinline__ unsigned f2tf(float f) {
    unsigned r; asm("cvt.rna.tf32.f32 %0, %1;" : "=r"(r) : "f"(f)); return r;
}
__device__ __forceinline__ void mma_tf32(float* d, const unsigned* a, const unsigned* b) {
    asm volatile("mma.sync.aligned.m16n8k8.row.col.f32.tf32.tf32.f32 "
        "{%0,%1,%2,%3}, {%4,%5,%6,%7}, {%8,%9}, {%0,%1,%2,%3};"
        : "+f"(d[0]), "+f"(d[1]), "+f"(d[2]), "+f"(d[3])
        : "r"(a[0]), "r"(a[1]), "r"(a[2]), "r"(a[3]), "r"(b[0]), "r"(b[1]));
}

// ---------------- CSR build ----------------
__global__ void k_zero_cnt() {
    int i = blockIdx.x * blockDim.x + threadIdx.x;
    if (i < N_NODES) g_cnt[i] = 0;
}
__global__ void k_count(const int* __restrict__ dst) {
    int e = blockIdx.x * blockDim.x + threadIdx.x;
    if (e < N_EDGES) atomicAdd(&g_cnt[dst[e]], 1);
}
__global__ void k_scan() {
    __shared__ int ss[1024];
    int tid = threadIdx.x;
    const int CH = (N_NODES + 1023) / 1024;
    int base = tid * CH;
    int s = 0;
    for (int i = 0; i < CH; ++i) { int idx = base + i; if (idx < N_NODES) s += g_cnt[idx]; }
    ss[tid] = s;
    __syncthreads();
    for (int off = 1; off < 1024; off <<= 1) {
        int v = (tid >= off) ? ss[tid - off] : 0;
        __syncthreads();
        ss[tid] += v;
        __syncthreads();
    }
    int run = ss[tid] - s;
    for (int i = 0; i < CH; ++i) {
        int idx = base + i;
        if (idx < N_NODES) {
            g_rowptr[idx] = run;
            g_cursor[idx] = run;
            int d = g_cnt[idx];
            g_rdeg[idx] = 1.0f / (float)(d > 0 ? d : 1);
            run += d;
        }
    }
    if (tid == 1023) g_rowptr[N_NODES] = ss[1023];
}
__global__ void k_fill(const int* __restrict__ src, const int* __restrict__ dst,
                       const float* __restrict__ ea) {
    int e = blockIdx.x * blockDim.x + threadIdx.x;
    if (e < N_EDGES) {
        int pos = atomicAdd(&g_cursor[dst[e]], 1);
        g_es[pos] = src[e];
        g_ep[pos] = ea[e];
    }
}

// ---------------- weight concatenation ----------------
__global__ void k_cat1(const float* __restrict__ W1, const float* __restrict__ R1,
                       const float* __restrict__ b1) {
    int i = blockIdx.x * blockDim.x + threadIdx.x;
    if (i < 256 * 192) {
        int k = i / 192, n = i % 192;
        float v;
        if (n < 64)       v = W1[k * 64 + n];
        else if (n < 128) v = W1[256 * 64 + k * 64 + (n - 64)];
        else              v = R1[k * 64 + (n - 128)];
        g_B1[i] = v;
    }
    if (i < 192) g_bias1[i] = (i < 128) ? 0.f : b1[i - 128];
}
__global__ void k_cat_h(const float* __restrict__ W, const float* __restrict__ R,
                        float* __restrict__ Bst) {
    int i = blockIdx.x * blockDim.x + threadIdx.x;
    if (i >= 192 * 64) return;
    int r = i / 64, c = i % 64;
    float v;
    if (r < 64)       v = R[r * 64 + c];
    else if (r < 128) v = W[(r - 64) * 64 + c];
    else              v = W[64 * 64 + (r - 128) * 64 + c];
    Bst[i] = v;
}
__global__ void k_cat2(const float* __restrict__ W2, const float* __restrict__ R2,
                       const float* __restrict__ b2) {
    int i = blockIdx.x * blockDim.x + threadIdx.x;
    if (i < 64 * 48) {
        int k = i / 48, n = i % 48;
        float v;
        if (n < 16)      v = W2[k * 16 + n];
        else if (n < 32) v = W2[64 * 16 + k * 16 + (n - 16)];
        else             v = R2[k * 16 + (n - 32)];
        g_B2[i] = v;
    }
    if (i < 48) g_bias2[i] = (i < 32) ? 0.f : b2[i - 32];
}

// ---------------- tf32 tensor-core GEMM: C[M,NTOT] = A[M,K] @ B[K,NTOT] + bias ----------------
template <int K, int NTOT, int BN>
__global__ void __launch_bounds__(256) k_mm(const float* __restrict__ A,
                                            const float* __restrict__ B,
                                            const float* __restrict__ bias,
                                            float* __restrict__ C) {
    constexpr int BM = 128, BK = 32;
    constexpr int WN = BN / 2, NF = WN / 8;
    __shared__ unsigned As[BM][BK + 4];   // stride 36: conflict-free a-frags
    __shared__ unsigned Bs[BK][BN + 8];   // stride BN+8: conflict-free b-frags

    const int tid = threadIdx.x;
    const int lane = tid & 31, warp = tid >> 5;
    const int wm = warp & 3, wn = warp >> 2;
    const int mBase = blockIdx.x * BM;
    const int nBase = blockIdx.y * BN;
    const int g = lane >> 2, t = lane & 3;

    float acc[2][NF][4];
#pragma unroll
    for (int mf = 0; mf < 2; ++mf)
#pragma unroll
        for (int nf = 0; nf < NF; ++nf)
#pragma unroll
            for (int q = 0; q < 4; ++q) acc[mf][nf][q] = 0.f;

    const int ar = tid >> 3, ac = (tid & 7) * 4;

    for (int k0 = 0; k0 < K; k0 += BK) {
#pragma unroll
        for (int p = 0; p < 4; ++p) {
            int row = p * 32 + ar;
            int gm = mBase + row;
            float4 v = make_float4(0.f, 0.f, 0.f, 0.f);
            if (gm < N_NODES) v = *reinterpret_cast<const float4*>(A + (size_t)gm * K + k0 + ac);
            unsigned* s = &As[row][ac];
            s[0] = f2tf(v.x); s[1] = f2tf(v.y); s[2] = f2tf(v.z); s[3] = f2tf(v.w);
        }
        for (int i = tid; i < BK * BN / 4; i += 256) {
            int bk = i / (BN / 4), bc = (i % (BN / 4)) * 4;
            float4 v = *reinterpret_cast<const float4*>(B + (size_t)(k0 + bk) * NTOT + nBase + bc);
            unsigned* s = &Bs[bk][bc];
            s[0] = f2tf(v.x); s[1] = f2tf(v.y); s[2] = f2tf(v.z); s[3] = f2tf(v.w);
        }
        __syncthreads();
#pragma unroll
        for (int kk = 0; kk < BK / 8; ++kk) {
            const int kb = kk * 8;
            unsigned a[2][4];
#pragma unroll
            for (int mf = 0; mf < 2; ++mf) {
                int r = wm * 32 + mf * 16;
                a[mf][0] = As[r + g][kb + t];
                a[mf][1] = As[r + g + 8][kb + t];
                a[mf][2] = As[r + g][kb + t + 4];
                a[mf][3] = As[r + g + 8][kb + t + 4];
            }
#pragma unroll
            for (int nf = 0; nf < NF; ++nf) {
                int n = wn * WN + nf * 8;
                unsigned b[2] = { Bs[kb + t][n + g], Bs[kb + t + 4][n + g] };
                mma_tf32(acc[0][nf], a[0], b);
                mma_tf32(acc[1][nf], a[1], b);
            }
        }
        __syncthreads();
    }
#pragma unroll
    for (int mf = 0; mf < 2; ++mf) {
#pragma unroll
        for (int nf = 0; nf < NF; ++nf) {
            int row = mBase + wm * 32 + mf * 16 + g;
            int col = nBase + wn * WN + nf * 8 + 2 * t;
            float b0 = bias[col], b1 = bias[col + 1];
            if (row < N_NODES)
                *reinterpret_cast<float2*>(C + (size_t)row * NTOT + col) =
                    make_float2(acc[mf][nf][0] + b0, acc[mf][nf][1] + b1);
            if (row + 8 < N_NODES)
                *reinterpret_cast<float2*>(C + (size_t)(row + 8) * NTOT + col) =
                    make_float2(acc[mf][nf][2] + b0, acc[mf][nf][3] + b1);
        }
    }
}

// ---------------- post-GEMM aggregation (conv1 / conv2): (1-p)*y0 + p*y1, mean, +xr, tanh ----------------
template <int C, bool ACT>
__global__ void __launch_bounds__(256) k_agg_after(float* __restrict__ out) {
    int gidx = blockIdx.x * blockDim.x + threadIdx.x;
    int node = gidx / C;
    int c = gidx % C;
    if (node >= N_NODES) return;
    int i = g_rowptr[node], end = g_rowptr[node + 1];
    float acc = 0.f;
    for (; i + 1 < end; i += 2) {
        int sA = g_es[i], sB = g_es[i + 1];
        float pA = g_ep[i], pB = g_ep[i + 1];
        const float* ra = g_Y + (size_t)sA * (3 * C);
        const float* rb = g_Y + (size_t)sB * (3 * C);
        float y0a = ra[c], y1a = ra[C + c];
        float y0b = rb[c], y1b = rb[C + c];
        acc += y0a + pA * (y1a - y0a);
        acc += y0b + pB * (y1b - y0b);
    }
    if (i < end) {
        int s = g_es[i];
        float p = g_ep[i];
        const float* r = g_Y + (size_t)s * (3 * C);
        float y0 = r[c], y1 = r[C + c];
        acc += y0 + p * (y1 - y0);
    }
    float v = fmaf(acc, g_rdeg[node], g_Y[(size_t)node * (3 * C) + 2 * C + c]);
    if (ACT) v = tanhf(v);
    out[(size_t)node * C + c] = v;
}

// ---------------- pre-GEMM aggregation (hidden): g_Y = [x | S0*rdeg | S1*rdeg] ----------------
__global__ void __launch_bounds__(256) k_preagg(const float* __restrict__ in) {
    int gidx = blockIdx.x * blockDim.x + threadIdx.x;
    int node = gidx >> 6;
    int c = gidx & 63;
    if (node >= N_NODES) return;
    int i = g_rowptr[node], end = g_rowptr[node + 1];
    float s_all = 0.f, s_p = 0.f;
    for (; i + 1 < end; i += 2) {
        int sA = g_es[i], sB = g_es[i + 1];
        float pA = g_ep[i], pB = g_ep[i + 1];
        float xA = in[(size_t)sA * 64 + c];
        float xB = in[(size_t)sB * 64 + c];
        s_all += xA + xB;
        s_p = fmaf(pA, xA, fmaf(pB, xB, s_p));
    }
    if (i < end) {
        int s = g_es[i];
        float p = g_ep[i];
        float xv = in[(size_t)s * 64 + c];
        s_all += xv;
        s_p = fmaf(p, xv, s_p);
    }
    float rd = g_rdeg[node];
    float* yr = g_Y + (size_t)node * 192;
    yr[c] = in[(size_t)node * 64 + c];
    yr[64 + c] = (s_all - s_p) * rd;   // S0/deg
    yr[128 + c] = s_p * rd;            // S1/deg
}

// ---------------- RK4 elementwise ----------------
__global__ void k_rkstage(float kAccMul, float curMul, int first) {
    int i = blockIdx.x * blockDim.x + threadIdx.x;
    if (i >= N_NODES * HID) return;
    float kv = g_kv[i];
    g_acc[i] = first ? (kAccMul * kv) : fmaf(kAccMul, kv, g_acc[i]);
    g_cur[i] = fmaf(curMul, kv, g_h[i]);
}
__global__ void k_rkfinal() {
    int i = blockIdx.x * blockDim.x + threadIdx.x;
    if (i >= N_NODES * HID) return;
    g_h[i] = fmaf(0.5f, g_acc[i] + g_kv[i], g_h[i]);
}

// ---------------- log_softmax over 16 classes ----------------
__global__ void k_lsm(float* __restrict__ out) {
    int warp = (blockIdx.x * blockDim.x + threadIdx.x) >> 5;
    int lane = threadIdx.x & 31;
    int row = warp * 2 + (lane >> 4);
    int c = lane & 15;
    if (row >= N_NODES) return;
    float v = g_logits[row * 16 + c];
    float m = v;
    for (int o = 8; o > 0; o >>= 1) m = fmaxf(m, __shfl_xor_sync(0xffffffffu, m, o, 16));
    float e = expf(v - m);
    float s = e;
    for (int o = 8; o > 0; o >>= 1) s += __shfl_xor_sync(0xffffffffu, s, o, 16);
    out[row * 16 + c] = v - m - logf(s);
}

// ---------------- launch ----------------
extern "C" void kernel_launch(void* const* d_in, const int* in_sizes, int n_in,
                              void* d_out, int out_size) {
    const float* x  = (const float*)d_in[0];
    const float* ea = (const float*)d_in[1];
    const int*   src = (const int*)d_in[2];
    const int*   dst = (const int*)d_in[3];
    const float* W1 = (const float*)d_in[4];
    const float* R1 = (const float*)d_in[5];
    const float* b1 = (const float*)d_in[6];
    const float* Wa = (const float*)d_in[7];
    const float* Ra = (const float*)d_in[8];
    const float* ba = (const float*)d_in[9];
    const float* Wb = (const float*)d_in[10];
    const float* Rb = (const float*)d_in[11];
    const float* bb = (const float*)d_in[12];
    const float* W2 = (const float*)d_in[13];
    const float* R2 = (const float*)d_in[14];
    const float* b2 = (const float*)d_in[15];
    float* out = (float*)d_out;

    float *h, *mid, *kv, *cur, *logits, *Y, *B1, *Bh1, *Bh2, *B2, *bias1, *bias2;
    cudaGetSymbolAddress((void**)&h, g_h);
    cudaGetSymbolAddress((void**)&mid, g_mid);
    cudaGetSymbolAddress((void**)&kv, g_kv);
    cudaGetSymbolAddress((void**)&cur, g_cur);
    cudaGetSymbolAddress((void**)&logits, g_logits);
    cudaGetSymbolAddress((void**)&Y, g_Y);
    cudaGetSymbolAddress((void**)&B1, g_B1);
    cudaGetSymbolAddress((void**)&Bh1, g_Bh1);
    cudaGetSymbolAddress((void**)&Bh2, g_Bh2);
    cudaGetSymbolAddress((void**)&B2, g_B2);
    cudaGetSymbolAddress((void**)&bias1, g_bias1);
    cudaGetSymbolAddress((void**)&bias2, g_bias2);

    // CSR build
    k_zero_cnt<<<(N_NODES + 255) / 256, 256>>>();
    k_count<<<N_EDGES / 256, 256>>>(dst);
    k_scan<<<1, 1024>>>();
    k_fill<<<N_EDGES / 256, 256>>>(src, dst, ea);

    // weight concatenation
    k_cat1<<<(256 * 192 + 255) / 256, 256>>>(W1, R1, b1);
    k_cat_h<<<(192 * 64 + 255) / 256, 256>>>(Wa, Ra, Bh1);
    k_cat_h<<<(192 * 64 + 255) / 256, 256>>>(Wb, Rb, Bh2);
    k_cat2<<<(64 * 48 + 255) / 256, 256>>>(W2, R2, b2);

    const int MG = (N_NODES + 127) / 128;     // gemm row-blocks: 391
    const int VG = (N_NODES * HID) / 256;     // elementwise grid
    const int AG64 = (N_NODES * HID) / 256;   // agg grid, 64 ch
    const int AG16 = (N_NODES * NCLS) / 256;  // agg grid, 16 ch

    // conv1: Y = x @ [W0|W1|R] (+b on R cols) -> agg -> h = tanh(...)
    k_mm<256, 192, 64><<<dim3(MG, 3), 256>>>(x, B1, bias1, Y);
    k_agg_after<64, true><<<AG64, 256>>>(h);

    // f(y): preagg -> [y|S0n|S1n] @ [R;W0;W1] + b   (twice)
    auto fstep = [&](const float* in, float* o) {
        k_preagg<<<AG64, 256>>>(in);
        k_mm<192, 64, 64><<<dim3(MG, 1), 256>>>(Y, Bh1, ba, mid);
        k_preagg<<<AG64, 256>>>(mid);
        k_mm<192, 64, 64><<<dim3(MG, 1), 256>>>(Y, Bh2, bb, o);
    };

    // RK4 over [0, 3]
    fstep(h, kv);                              // k1
    k_rkstage<<<VG, 256>>>(1.f, 1.5f, 1);
    fstep(cur, kv);                            // k2
    k_rkstage<<<VG, 256>>>(2.f, 1.5f, 0);
    fstep(cur, kv);                            // k3
    k_rkstage<<<VG, 256>>>(2.f, 3.0f, 0);
    fstep(cur, kv);                            // k4
    k_rkfinal<<<VG, 256>>>();

    // conv2 + log_softmax
    k_mm<64, 48, 48><<<dim3(MG, 1), 256>>>(h, B2, bias2, Y);
    k_agg_after<16, true><<<AG16, 256>>>(logits);
    k_lsm<<<(N_NODES + 15) / 16, 256>>>(out);
}

// round 5
// speedup vs baseline: 2.1338x; 1.5084x over previous
#include <cuda_runtime.h>
#include <cuda_bf16.h>
#include <cstdint>

#define N_NODES 50000
#define N_EDGES 800000
#define F_IN 256
#define HID 64
#define NCLS 16
#define NB_SCAN 196   // ceil(50000/256)

// ---------------- scratch ----------------
__device__ int   g_cnt[N_NODES];
__device__ int   g_rowptr[N_NODES + 1];
__device__ int   g_cursor[N_NODES];
__device__ int   g_bsum[256];
__device__ int   g_boff[256];
__device__ int   g_es[N_EDGES];
__device__ float g_ep[N_EDGES];
__device__ float g_rdeg[N_NODES];

__device__ __align__(16) float g_h[(size_t)N_NODES * HID];
__device__ __align__(16) float g_mid[(size_t)N_NODES * HID];
__device__ __align__(16) float g_acc[(size_t)N_NODES * HID];
__device__ __align__(16) float g_cur[(size_t)N_NODES * HID];
__device__ __align__(16) __nv_bfloat16 g_hb[(size_t)N_NODES * HID];
__device__ __align__(16) __nv_bfloat16 g_midb[(size_t)N_NODES * HID];
__device__ __align__(16) __nv_bfloat16 g_curb[(size_t)N_NODES * HID];
__device__ __align__(16) float g_Ypre[(size_t)N_NODES * 128];      // [S0n | S1n]
__device__ __align__(16) __nv_bfloat16 g_c1[(size_t)N_NODES * 128]; // interleaved y0/y1, conv1
__device__ __align__(16) float g_xr1[(size_t)N_NODES * HID];
__device__ __align__(16) __nv_bfloat16 g_c2[(size_t)N_NODES * 32];  // interleaved y0/y1, conv2
__device__ __align__(16) float g_xr2[(size_t)N_NODES * NCLS];
// concatenated weights
__device__ __align__(16) float g_B1[256 * 192];    // cols [W1_0 | W1_1 | R1]
__device__ __align__(16) float g_Bh1[192 * 64];    // rows [Ra; Wa0; Wa1]
__device__ __align__(16) float g_Bh2[192 * 64];    // rows [Rb; Wb0; Wb1]
__device__ __align__(16) float g_B2[64 * 48];      // cols [W2_0 | W2_1 | R2]

// ---------------- tf32 mma helpers ----------------
__device__ __forceinline__ unsigned f2tf(float f) {
    unsigned r; asm("cvt.rna.tf32.f32 %0, %1;" : "=r"(r) : "f"(f)); return r;
}
__device__ __forceinline__ void mma_tf32(float* d, const unsigned* a, const unsigned* b) {
    asm volatile("mma.sync.aligned.m16n8k8.row.col.f32.tf32.tf32.f32 "
        "{%0,%1,%2,%3}, {%4,%5,%6,%7}, {%8,%9}, {%0,%1,%2,%3};"
        : "+f"(d[0]), "+f"(d[1]), "+f"(d[2]), "+f"(d[3])
        : "r"(a[0]), "r"(a[1]), "r"(a[2]), "r"(a[3]), "r"(b[0]), "r"(b[1]));
}

// ---------------- CSR build ----------------
__global__ void k_zero_cnt() {
    int i = blockIdx.x * blockDim.x + threadIdx.x;
    if (i < N_NODES) g_cnt[i] = 0;
}
__global__ void k_count(const int* __restrict__ dst) {
    int e = blockIdx.x * blockDim.x + threadIdx.x;
    if (e < N_EDGES) atomicAdd(&g_cnt[dst[e]], 1);
}
__global__ void k_bsum() {
    __shared__ int ss[256];
    int t = threadIdx.x;
    int idx = blockIdx.x * 256 + t;
    ss[t] = (idx < N_NODES) ? g_cnt[idx] : 0;
    __syncthreads();
    for (int off = 128; off > 0; off >>= 1) {
        if (t < off) ss[t] += ss[t + off];
        __syncthreads();
    }
    if (t == 0) g_bsum[blockIdx.x] = ss[0];
}
__global__ void k_bscan() {
    __shared__ int ss[256];
    int t = threadIdx.x;
    int v = (t < NB_SCAN) ? g_bsum[t] : 0;
    ss[t] = v;
    __syncthreads();
    for (int off = 1; off < 256; off <<= 1) {
        int u = (t >= off) ? ss[t - off] : 0;
        __syncthreads();
        ss[t] += u;
        __syncthreads();
    }
    g_boff[t] = ss[t] - v;
    if (t == 255) g_rowptr[N_NODES] = ss[255];
}
__global__ void k_bapply() {
    __shared__ int ss[256];
    int t = threadIdx.x;
    int idx = blockIdx.x * 256 + t;
    int v = (idx < N_NODES) ? g_cnt[idx] : 0;
    ss[t] = v;
    __syncthreads();
    for (int off = 1; off < 256; off <<= 1) {
        int u = (t >= off) ? ss[t - off] : 0;
        __syncthreads();
        ss[t] += u;
        __syncthreads();
    }
    if (idx < N_NODES) {
        int base = g_boff[blockIdx.x] + ss[t] - v;
        g_rowptr[idx] = base;
        g_cursor[idx] = base;
        g_rdeg[idx] = 1.0f / (float)(v > 0 ? v : 1);
    }
}
__global__ void k_fill(const int* __restrict__ src, const int* __restrict__ dst,
                       const float* __restrict__ ea) {
    int e = blockIdx.x * blockDim.x + threadIdx.x;
    if (e < N_EDGES) {
        int pos = atomicAdd(&g_cursor[dst[e]], 1);
        g_es[pos] = src[e];
        g_ep[pos] = ea[e];
    }
}

// ---------------- weight concatenation (one kernel) ----------------
__global__ void k_cat_all(const float* __restrict__ W1, const float* __restrict__ R1,
                          const float* __restrict__ Wa, const float* __restrict__ Ra,
                          const float* __restrict__ Wb, const float* __restrict__ Rb,
                          const float* __restrict__ W2, const float* __restrict__ R2) {
    int i = blockIdx.x * blockDim.x + threadIdx.x;
    if (i < 256 * 192) {
        int k = i / 192, n = i % 192;
        float v;
        if (n < 64)       v = W1[k * 64 + n];
        else if (n < 128) v = W1[256 * 64 + k * 64 + (n - 64)];
        else              v = R1[k * 64 + (n - 128)];
        g_B1[i] = v;
    }
    if (i < 192 * 64) {
        int r = i / 64, c = i % 64;
        float va, vb;
        if (r < 64)       { va = Ra[r * 64 + c];                 vb = Rb[r * 64 + c]; }
        else if (r < 128) { va = Wa[(r - 64) * 64 + c];          vb = Wb[(r - 64) * 64 + c]; }
        else              { va = Wa[64 * 64 + (r - 128) * 64 + c]; vb = Wb[64 * 64 + (r - 128) * 64 + c]; }
        g_Bh1[i] = va;
        g_Bh2[i] = vb;
    }
    if (i < 64 * 48) {
        int k = i / 48, n = i % 48;
        float v;
        if (n < 16)      v = W2[k * 16 + n];
        else if (n < 32) v = W2[64 * 16 + k * 16 + (n - 16)];
        else             v = R2[k * 16 + (n - 32)];
        g_B2[i] = v;
    }
}

// ---------------- tf32 GEMM with fused epilogues ----------------
// EPI: 0=conv1 (bf16 interleaved y0/y1 + xr), 1=mid (fp32+bf16), 2=RK stage, 3=conv2
template <int K, int NTOT, int BN, int ASPLIT, int EPI>
__global__ void __launch_bounds__(256) k_mm(const float* __restrict__ A,
                                            const float* __restrict__ A2,
                                            const float* __restrict__ B,
                                            const float* __restrict__ bias,
                                            float* __restrict__ Cf,
                                            __nv_bfloat16* __restrict__ Cb,
                                            float* __restrict__ aux,
                                            int estage, float curMul) {
    constexpr int BM = 128, BK = 32;
    constexpr int WN = BN / 2, NF = WN / 8;
    __shared__ unsigned As[BM][BK + 4];
    __shared__ unsigned Bs[BK][BN + 8];

    const int tid = threadIdx.x;
    const int lane = tid & 31, warp = tid >> 5;
    const int wm = warp & 3, wn = warp >> 2;
    const int mBase = blockIdx.x * BM;
    const int nBase = blockIdx.y * BN;
    const int g = lane >> 2, t = lane & 3;

    float acc[2][NF][4];
#pragma unroll
    for (int mf = 0; mf < 2; ++mf)
#pragma unroll
        for (int nf = 0; nf < NF; ++nf)
#pragma unroll
            for (int q = 0; q < 4; ++q) acc[mf][nf][q] = 0.f;

    const int ar = tid >> 3, ac = (tid & 7) * 4;

    for (int k0 = 0; k0 < K; k0 += BK) {
#pragma unroll
        for (int p = 0; p < 4; ++p) {
            int row = p * 32 + ar;
            int gm = mBase + row;
            float4 v = make_float4(0.f, 0.f, 0.f, 0.f);
            if (gm < N_NODES) {
                if (ASPLIT) {
                    if (k0 < 64) v = *reinterpret_cast<const float4*>(A  + (size_t)gm * 64  + k0 + ac);
                    else         v = *reinterpret_cast<const float4*>(A2 + (size_t)gm * 128 + (k0 - 64) + ac);
                } else {
                    v = *reinterpret_cast<const float4*>(A + (size_t)gm * K + k0 + ac);
                }
            }
            unsigned* s = &As[row][ac];
            s[0] = f2tf(v.x); s[1] = f2tf(v.y); s[2] = f2tf(v.z); s[3] = f2tf(v.w);
        }
        for (int i = tid; i < BK * BN / 4; i += 256) {
            int bk = i / (BN / 4), bc = (i % (BN / 4)) * 4;
            float4 v = *reinterpret_cast<const float4*>(B + (size_t)(k0 + bk) * NTOT + nBase + bc);
            unsigned* s = &Bs[bk][bc];
            s[0] = f2tf(v.x); s[1] = f2tf(v.y); s[2] = f2tf(v.z); s[3] = f2tf(v.w);
        }
        __syncthreads();
#pragma unroll
        for (int kk = 0; kk < BK / 8; ++kk) {
            const int kb = kk * 8;
            unsigned a[2][4];
#pragma unroll
            for (int mf = 0; mf < 2; ++mf) {
                int r = wm * 32 + mf * 16;
                a[mf][0] = As[r + g][kb + t];
                a[mf][1] = As[r + g + 8][kb + t];
                a[mf][2] = As[r + g][kb + t + 4];
                a[mf][3] = As[r + g + 8][kb + t + 4];
            }
#pragma unroll
            for (int nf = 0; nf < NF; ++nf) {
                int n = wn * WN + nf * 8;
                unsigned b[2] = { Bs[kb + t][n + g], Bs[kb + t + 4][n + g] };
                mma_tf32(acc[0][nf], a[0], b);
                mma_tf32(acc[1][nf], a[1], b);
            }
        }
        __syncthreads();
    }

    const int by = blockIdx.y;
    auto emit = [&](int row, int col, float a0, float a1) {
        if (row >= N_NODES) return;
        if (EPI == 0) {
            int c = col - (by << 6);
            if (by < 2) {
                Cb[(size_t)row * 128 + 2 * c + by]       = __float2bfloat16(a0);
                Cb[(size_t)row * 128 + 2 * (c + 1) + by] = __float2bfloat16(a1);
            } else {
                *reinterpret_cast<float2*>(aux + (size_t)row * 64 + c) =
                    make_float2(a0 + bias[c], a1 + bias[c + 1]);
            }
        } else if (EPI == 1) {
            float2 v = make_float2(a0 + bias[col], a1 + bias[col + 1]);
            *reinterpret_cast<float2*>(Cf + (size_t)row * 64 + col) = v;
            *reinterpret_cast<__nv_bfloat162*>(Cb + (size_t)row * 64 + col) = __float22bfloat162_rn(v);
        } else if (EPI == 2) {
            float2 kv = make_float2(a0 + bias[col], a1 + bias[col + 1]);
            size_t idx = (size_t)row * 64 + col;
            float2 h2 = *reinterpret_cast<const float2*>(g_h + idx);
            if (estage == 4) {
                float2 a2 = *reinterpret_cast<const float2*>(g_acc + idx);
                *reinterpret_cast<float2*>(g_h + idx) =
                    make_float2(h2.x + 0.5f * (a2.x + kv.x), h2.y + 0.5f * (a2.y + kv.y));
            } else {
                float2 a2;
                if (estage == 1) a2 = kv;
                else {
                    a2 = *reinterpret_cast<const float2*>(g_acc + idx);
                    a2.x = fmaf(2.f, kv.x, a2.x); a2.y = fmaf(2.f, kv.y, a2.y);
                }
                *reinterpret_cast<float2*>(g_acc + idx) = a2;
                float2 c2 = make_float2(fmaf(curMul, kv.x, h2.x), fmaf(curMul, kv.y, h2.y));
                *reinterpret_cast<float2*>(g_cur + idx) = c2;
                *reinterpret_cast<__nv_bfloat162*>(g_curb + idx) = __float22bfloat162_rn(c2);
            }
        } else {  // EPI == 3 (conv2)
            if (col < 32) {
                int sec = col >> 4, c = col & 15;
                Cb[(size_t)row * 32 + 2 * c + sec]       = __float2bfloat16(a0);
                Cb[(size_t)row * 32 + 2 * (c + 1) + sec] = __float2bfloat16(a1);
            } else {
                *reinterpret_cast<float2*>(aux + (size_t)row * 16 + (col - 32)) =
                    make_float2(a0 + bias[col - 32], a1 + bias[col - 31]);
            }
        }
    };

#pragma unroll
    for (int mf = 0; mf < 2; ++mf)
#pragma unroll
        for (int nf = 0; nf < NF; ++nf) {
            int row = mBase + wm * 32 + mf * 16 + g;
            int col = nBase + wn * WN + nf * 8 + 2 * t;
            emit(row, col, acc[mf][nf][0], acc[mf][nf][1]);
            emit(row + 8, col, acc[mf][nf][2], acc[mf][nf][3]);
        }
}

// ---------------- conv1 aggregation: warp/node, bf16 interleaved gather, tanh ----------------
__global__ void __launch_bounds__(256) k_agg1() {
    int w = (blockIdx.x * 256 + threadIdx.x) >> 5;
    int lane = threadIdx.x & 31;
    if (w >= N_NODES) return;
    int i = g_rowptr[w], end = g_rowptr[w + 1];
    float a0 = 0.f, a1 = 0.f;
    for (; i + 1 < end; i += 2) {
        int sA = g_es[i], sB = g_es[i + 1];
        float pA = g_ep[i], pB = g_ep[i + 1];
        uint2 uA = *reinterpret_cast<const uint2*>(g_c1 + (size_t)sA * 128 + 4 * lane);
        uint2 uB = *reinterpret_cast<const uint2*>(g_c1 + (size_t)sB * 128 + 4 * lane);
        float2 vA0 = __bfloat1622float2(*reinterpret_cast<__nv_bfloat162*>(&uA.x));
        float2 vA1 = __bfloat1622float2(*reinterpret_cast<__nv_bfloat162*>(&uA.y));
        float2 vB0 = __bfloat1622float2(*reinterpret_cast<__nv_bfloat162*>(&uB.x));
        float2 vB1 = __bfloat1622float2(*reinterpret_cast<__nv_bfloat162*>(&uB.y));
        a0 += fmaf(pA, vA0.y - vA0.x, vA0.x) + fmaf(pB, vB0.y - vB0.x, vB0.x);
        a1 += fmaf(pA, vA1.y - vA1.x, vA1.x) + fmaf(pB, vB1.y - vB1.x, vB1.x);
    }
    if (i < end) {
        int s = g_es[i];
        float p = g_ep[i];
        uint2 u = *reinterpret_cast<const uint2*>(g_c1 + (size_t)s * 128 + 4 * lane);
        float2 v0 = __bfloat1622float2(*reinterpret_cast<__nv_bfloat162*>(&u.x));
        float2 v1 = __bfloat1622float2(*reinterpret_cast<__nv_bfloat162*>(&u.y));
        a0 += fmaf(p, v0.y - v0.x, v0.x);
        a1 += fmaf(p, v1.y - v1.x, v1.x);
    }
    float rd = g_rdeg[w];
    float2 xr = *reinterpret_cast<const float2*>(g_xr1 + (size_t)w * 64 + 2 * lane);
    float2 hv = make_float2(tanhf(fmaf(a0, rd, xr.x)), tanhf(fmaf(a1, rd, xr.y)));
    *reinterpret_cast<float2*>(g_h + (size_t)w * 64 + 2 * lane) = hv;
    *reinterpret_cast<__nv_bfloat162*>(g_hb + (size_t)w * 64 + 2 * lane) = __float22bfloat162_rn(hv);
}

// ---------------- hidden pre-aggregation: warp/node, bf16 gather -> [S0n|S1n] ----------------
__global__ void __launch_bounds__(256) k_preagg(const __nv_bfloat16* __restrict__ inb) {
    int w = (blockIdx.x * 256 + threadIdx.x) >> 5;
    int lane = threadIdx.x & 31;
    if (w >= N_NODES) return;
    int i = g_rowptr[w], end = g_rowptr[w + 1];
    float sa0 = 0.f, sa1 = 0.f, sp0 = 0.f, sp1 = 0.f;
    for (; i + 1 < end; i += 2) {
        int sA = g_es[i], sB = g_es[i + 1];
        float pA = g_ep[i], pB = g_ep[i + 1];
        float2 xA = __bfloat1622float2(*reinterpret_cast<const __nv_bfloat162*>(inb + (size_t)sA * 64 + 2 * lane));
        float2 xB = __bfloat1622float2(*reinterpret_cast<const __nv_bfloat162*>(inb + (size_t)sB * 64 + 2 * lane));
        sa0 += xA.x + xB.x;
        sa1 += xA.y + xB.y;
        sp0 = fmaf(pA, xA.x, fmaf(pB, xB.x, sp0));
        sp1 = fmaf(pA, xA.y, fmaf(pB, xB.y, sp1));
    }
    if (i < end) {
        int s = g_es[i];
        float p = g_ep[i];
        float2 xv = __bfloat1622float2(*reinterpret_cast<const __nv_bfloat162*>(inb + (size_t)s * 64 + 2 * lane));
        sa0 += xv.x; sa1 += xv.y;
        sp0 = fmaf(p, xv.x, sp0);
        sp1 = fmaf(p, xv.y, sp1);
    }
    float rd = g_rdeg[w];
    float* yr = g_Ypre + (size_t)w * 128;
    *reinterpret_cast<float2*>(yr + 2 * lane)      = make_float2((sa0 - sp0) * rd, (sa1 - sp1) * rd);
    *reinterpret_cast<float2*>(yr + 64 + 2 * lane) = make_float2(sp0 * rd, sp1 * rd);
}

// ---------------- conv2 aggregation + log_softmax (half-warp/node) ----------------
__global__ void __launch_bounds__(256) k_agg2_lsm(float* __restrict__ out) {
    int hw = (blockIdx.x * 256 + threadIdx.x) >> 4;
    int c = threadIdx.x & 15;
    if (hw >= N_NODES) return;
    int i = g_rowptr[hw], end = g_rowptr[hw + 1];
    float acc = 0.f;
    for (; i + 1 < end; i += 2) {
        int sA = g_es[i], sB = g_es[i + 1];
        float pA = g_ep[i], pB = g_ep[i + 1];
        float2 vA = __bfloat1622float2(*reinterpret_cast<const __nv_bfloat162*>(g_c2 + (size_t)sA * 32 + 2 * c));
        float2 vB = __bfloat1622float2(*reinterpret_cast<const __nv_bfloat162*>(g_c2 + (size_t)sB * 32 + 2 * c));
        acc += fmaf(pA, vA.y - vA.x, vA.x) + fmaf(pB, vB.y - vB.x, vB.x);
    }
    if (i < end) {
        int s = g_es[i];
        float p = g_ep[i];
        float2 v = __bfloat1622float2(*reinterpret_cast<const __nv_bfloat162*>(g_c2 + (size_t)s * 32 + 2 * c));
        acc += fmaf(p, v.y - v.x, v.x);
    }
    float v = tanhf(fmaf(acc, g_rdeg[hw], g_xr2[(size_t)hw * 16 + c]));
    float m = v;
    for (int o = 8; o > 0; o >>= 1) m = fmaxf(m, __shfl_xor_sync(0xffffffffu, m, o, 16));
    float e = expf(v - m);
    float s = e;
    for (int o = 8; o > 0; o >>= 1) s += __shfl_xor_sync(0xffffffffu, s, o, 16);
    out[(size_t)hw * 16 + c] = v - m - logf(s);
}

// ---------------- launch ----------------
extern "C" void kernel_launch(void* const* d_in, const int* in_sizes, int n_in,
                              void* d_out, int out_size) {
    const float* x  = (const float*)d_in[0];
    const float* ea = (const float*)d_in[1];
    const int*   src = (const int*)d_in[2];
    const int*   dst = (const int*)d_in[3];
    const float* W1 = (const float*)d_in[4];
    const float* R1 = (const float*)d_in[5];
    const float* b1 = (const float*)d_in[6];
    const float* Wa = (const float*)d_in[7];
    const float* Ra = (const float*)d_in[8];
    const float* ba = (const float*)d_in[9];
    const float* Wb = (const float*)d_in[10];
    const float* Rb = (const float*)d_in[11];
    const float* bb = (const float*)d_in[12];
    const float* W2 = (const float*)d_in[13];
    const float* R2 = (const float*)d_in[14];
    const float* b2 = (const float*)d_in[15];
    float* out = (float*)d_out;

    float *h, *mid, *cur, *Ypre, *B1, *Bh1, *Bh2, *B2, *xr1, *xr2;
    __nv_bfloat16 *hb, *midb, *curb, *c1, *c2;
    cudaGetSymbolAddress((void**)&h, g_h);
    cudaGetSymbolAddress((void**)&mid, g_mid);
    cudaGetSymbolAddress((void**)&cur, g_cur);
    cudaGetSymbolAddress((void**)&hb, g_hb);
    cudaGetSymbolAddress((void**)&midb, g_midb);
    cudaGetSymbolAddress((void**)&curb, g_curb);
    cudaGetSymbolAddress((void**)&Ypre, g_Ypre);
    cudaGetSymbolAddress((void**)&B1, g_B1);
    cudaGetSymbolAddress((void**)&Bh1, g_Bh1);
    cudaGetSymbolAddress((void**)&Bh2, g_Bh2);
    cudaGetSymbolAddress((void**)&B2, g_B2);
    cudaGetSymbolAddress((void**)&c1, g_c1);
    cudaGetSymbolAddress((void**)&c2, g_c2);
    cudaGetSymbolAddress((void**)&xr1, g_xr1);
    cudaGetSymbolAddress((void**)&xr2, g_xr2);

    // CSR build
    k_zero_cnt<<<NB_SCAN, 256>>>();
    k_count<<<N_EDGES / 256, 256>>>(dst);
    k_bsum<<<NB_SCAN, 256>>>();
    k_bscan<<<1, 256>>>();
    k_bapply<<<NB_SCAN, 256>>>();
    k_fill<<<N_EDGES / 256, 256>>>(src, dst, ea);
    k_cat_all<<<192, 256>>>(W1, R1, Wa, Ra, Wb, Rb, W2, R2);

    const int MG = (N_NODES + 127) / 128;
    const int WG = (N_NODES * 32 + 255) / 256;   // warp-per-node grids
    const int HG = (N_NODES * 16 + 255) / 256;   // half-warp-per-node

    // conv1
    k_mm<256, 192, 64, 0, 0><<<dim3(MG, 3), 256>>>(x, nullptr, B1, b1, nullptr, c1, xr1, 0, 0.f);
    k_agg1<<<WG, 256>>>();

    // RK4 stages: each = preagg(in_b) -> GEMM1 -> preagg(midb) -> GEMM2(epilogue does RK math)
    auto fstep = [&](const float* inf, const __nv_bfloat16* inb, int stage, float curMul) {
        k_preagg<<<WG, 256>>>(inb);
        k_mm<192, 64, 64, 1, 1><<<dim3(MG, 1), 256>>>(inf, Ypre, Bh1, ba, mid, midb, nullptr, 0, 0.f);
        k_preagg<<<WG, 256>>>(midb);
        k_mm<192, 64, 64, 1, 2><<<dim3(MG, 1), 256>>>(mid, Ypre, Bh2, bb, nullptr, nullptr, nullptr, stage, curMul);
    };
    fstep(h, hb, 1, 1.5f);
    fstep(cur, curb, 2, 1.5f);
    fstep(cur, curb, 3, 3.0f);
    fstep(cur, curb, 4, 0.f);

    // conv2 + log_softmax
    k_mm<64, 48, 48, 0, 3><<<dim3(MG, 1), 256>>>(h, nullptr, B2, b2, nullptr, c2, xr2, 0, 0.f);
    k_agg2_lsm<<<HG, 256>>>(out);
}